// round 7
// baseline (speedup 1.0000x reference)
#include <cuda_runtime.h>
#include <math.h>

// Problem constants
#define BB 4
#define TT 4096
#define CC 1024
#define HH 64
#define BQ 64
#define BKT 64
#define NT (TT / BQ)
#define CHUNK 8
#define MAXSPL 8

typedef unsigned long long u64;

// ---- packed fp32x2 helpers (ptxas never emits FFMA2 from C++) ----
__device__ __forceinline__ void fma2(u64& d, u64 a, u64 b) {
    asm("fma.rn.f32x2 %0, %1, %2, %0;" : "+l"(d) : "l"(a), "l"(b));
}
__device__ __forceinline__ void mul2(u64& d, u64 a, u64 b) {
    asm("mul.rn.f32x2 %0, %1, %2;" : "=l"(d) : "l"(a), "l"(b));
}
__device__ __forceinline__ u64 pack2(float lo, float hi) {
    u64 d; asm("mov.b64 %0, {%1, %2};" : "=l"(d) : "f"(lo), "f"(hi)); return d;
}
__device__ __forceinline__ float2 unpack2(u64 v) {
    float2 r; asm("mov.b64 {%0, %1}, %2;" : "=f"(r.x), "=f"(r.y) : "l"(v)); return r;
}

// Scratch (no cudaMalloc allowed)
__device__ float g_q[BB * TT * HH];
__device__ float g_k[BB * TT * HH];
__device__ float g_v[BB * TT * HH];
__device__ float g_opart[BB * NT * MAXSPL * BQ * HH];
__device__ float g_mpart[BB * NT * MAXSPL * BQ];
__device__ float g_lpart[BB * NT * MAXSPL * BQ];

// ---------------------------------------------------------------------------
// Projection GEMM via FFMA2: out[16384,64] = x[16384,1024] @ W[1024,64]
// A stored duplicated in smem so the scalar operand is a free (a,a) pair;
// B pairs (c,c+1) are contiguous in row-major W. grid (128, 3), block 256.
// ---------------------------------------------------------------------------
__global__ __launch_bounds__(256) void proj_kernel(
    const float* __restrict__ x,
    const float* __restrict__ Wk,
    const float* __restrict__ Wq,
    const float* __restrict__ Wv)
{
    __shared__ __align__(16) float As2[128 * 68];  // dup format: [row][2k..2k+1]=(a,a)
    __shared__ __align__(16) float Bs[32 * 64];

    const float* W;
    float* out;
    if (blockIdx.y == 0)      { W = Wq; out = g_q; }
    else if (blockIdx.y == 1) { W = Wk; out = g_k; }
    else                      { W = Wv; out = g_v; }

    const int rowBase = blockIdx.x * 128;
    const int tid = threadIdx.x;
    const int ty = tid >> 4;
    const int tx = tid & 15;

    u64 acc[8][2];
#pragma unroll
    for (int i = 0; i < 8; i++) { acc[i][0] = 0ULL; acc[i][1] = 0ULL; }

    const int lr  = tid >> 3;
    const int lf4 = (tid & 7) * 4;
    const int lkk = tid >> 4;
    const int lh4 = (tid & 15) * 4;

    for (int k0 = 0; k0 < CC; k0 += 32) {
#pragma unroll
        for (int it = 0; it < 4; it++) {
            int row = lr + it * 32;
            float4 v = *(const float4*)(x + (size_t)(rowBase + row) * CC + k0 + lf4);
            ulonglong2* dst = (ulonglong2*)&As2[row * 68 + 2 * lf4];
            dst[0] = make_ulonglong2(pack2(v.x, v.x), pack2(v.y, v.y));
            dst[1] = make_ulonglong2(pack2(v.z, v.z), pack2(v.w, v.w));
        }
#pragma unroll
        for (int it = 0; it < 2; it++) {
            *(float4*)(&Bs[(lkk + it * 16) * 64 + lh4]) =
                *(const float4*)(W + (size_t)(k0 + lkk + it * 16) * HH + lh4);
        }
        __syncthreads();

#pragma unroll 4
        for (int kk = 0; kk < 32; kk++) {
            ulonglong2 b = *(const ulonglong2*)(&Bs[kk * 64 + tx * 4]);
#pragma unroll
            for (int i = 0; i < 8; i++) {
                u64 a = *(const u64*)(&As2[(ty * 8 + i) * 68 + 2 * kk]);
                fma2(acc[i][0], a, b.x);
                fma2(acc[i][1], a, b.y);
            }
        }
        __syncthreads();
    }

#pragma unroll
    for (int i = 0; i < 8; i++) {
        float2 c01 = unpack2(acc[i][0]);
        float2 c23 = unpack2(acc[i][1]);
        *(float4*)(out + (size_t)(rowBase + ty * 8 + i) * HH + tx * 4) =
            make_float4(c01.x, c01.y, c23.x, c23.y);
    }
}

// ---------------------------------------------------------------------------
// Split-KV flash attention, FFMA2 everywhere.
// S-phase: h-packed (lo=even h, hi=odd h), operands contiguous.
// O-phase: c-packed; P stored duplicated in smem (Ps2 aliases Qs+Ks,
// Q reloaded each kt). Static smem = 48 KB. grid (NT, MAXSPL, BB).
// ---------------------------------------------------------------------------
__global__ __launch_bounds__(256, 2) void attn_kernel()
{
    __shared__ __align__(16) float sm[3 * BQ * HH];  // 48 KB
    float* Qs  = sm;              // 16 KB
    float* Ks  = sm + 4096;       // 16 KB
    float* Vs  = sm + 8192;       // 16 KB
    float* Ps2 = sm;              // 32 KB, aliases Qs+Ks (sync-guarded)

    const int qt    = blockIdx.x;
    const int split = blockIdx.y;
    const int b     = blockIdx.z;
    const int nspl  = (qt + CHUNK) / CHUNK;
    if (split >= nspl) return;

    const int ktBeg = split * CHUNK;
    const int ktEnd = min(ktBeg + CHUNK, qt + 1);
    const int qbase = qt * BQ;

    const float* qg = g_q + ((size_t)b * TT + qbase) * HH;
    const float* kg = g_k + (size_t)b * TT * HH;
    const float* vg = g_v + (size_t)b * TT * HH;

    const int tid = threadIdx.x;
    const int ty = tid >> 4;
    const int tx = tid & 15;

    float m_i[4], l_i[4];
    u64 o2[4][2];
#pragma unroll
    for (int i = 0; i < 4; i++) {
        m_i[i] = -3.0e38f;
        l_i[i] = 0.0f;
        o2[i][0] = 0ULL;
        o2[i][1] = 0ULL;
    }

    const float scale = 0.03125f;  // 1024^-0.5

    for (int kt = ktBeg; kt < ktEnd; kt++) {
        const int kbase = kt * BKT;

        __syncthreads();  // previous O-phase reads of Ps2/Vs complete
        // Load Q (reloaded every kt since Ps2 overwrote it), K, V
#pragma unroll
        for (int it = 0; it < 4; it++) {
            int idx = tid + it * 256;
            int row = idx >> 4;
            int h4  = (idx & 15) * 4;
            int swz = (h4 + 4 * row) & 63;
            float4 qv = *(const float4*)(qg + row * HH + h4);
            *(float4*)(&Qs[row * HH + swz]) = qv;
            float4 kv = *(const float4*)(kg + (size_t)(kbase + row) * HH + h4);
            *(float4*)(&Ks[row * HH + swz]) = kv;
            float4 vv = *(const float4*)(vg + (size_t)(kbase + row) * HH + h4);
            *(float4*)(&Vs[row * HH + h4]) = vv;
        }
        __syncthreads();

        // ---- S = Q K^T, h-packed FFMA2 ----
        u64 s2[4][4];
#pragma unroll
        for (int i = 0; i < 4; i++)
#pragma unroll
            for (int j = 0; j < 4; j++) s2[i][j] = 0ULL;

#pragma unroll 2
        for (int h = 0; h < HH; h += 4) {
            ulonglong2 q2[4], k2[4];
#pragma unroll
            for (int i = 0; i < 4; i++) {
                int r = ty * 4 + i;
                q2[i] = *(const ulonglong2*)(&Qs[r * HH + ((h + 4 * r) & 63)]);
            }
#pragma unroll
            for (int j = 0; j < 4; j++) {
                int c = tx * 4 + j;
                k2[j] = *(const ulonglong2*)(&Ks[c * HH + ((h + 4 * c) & 63)]);
            }
#pragma unroll
            for (int i = 0; i < 4; i++)
#pragma unroll
                for (int j = 0; j < 4; j++) {
                    fma2(s2[i][j], q2[i].x, k2[j].x);
                    fma2(s2[i][j], q2[i].y, k2[j].y);
                }
        }

        // ---- mask + online softmax ----
        const bool diag = (kt == qt);
        float p[4][4];
#pragma unroll
        for (int i = 0; i < 4; i++) {
            const int row = qbase + ty * 4 + i;
            float sv[4];
            float mx = -3.0e38f;
#pragma unroll
            for (int j = 0; j < 4; j++) {
                float2 ss = unpack2(s2[i][j]);
                float v = (ss.x + ss.y) * scale;
                if (diag && (kbase + tx * 4 + j) > row) v = -3.0e38f;
                sv[j] = v;
                mx = fmaxf(mx, v);
            }
#pragma unroll
            for (int off = 8; off; off >>= 1)
                mx = fmaxf(mx, __shfl_xor_sync(0xffffffffu, mx, off));
            const float mnew = fmaxf(m_i[i], mx);
            const float corr = __expf(m_i[i] - mnew);
            float rsum = 0.0f;
#pragma unroll
            for (int j = 0; j < 4; j++) {
                float pv = __expf(sv[j] - mnew);
                p[i][j] = pv;
                rsum += pv;
            }
#pragma unroll
            for (int off = 8; off; off >>= 1)
                rsum += __shfl_xor_sync(0xffffffffu, rsum, off);
            l_i[i] = l_i[i] * corr + rsum;
            m_i[i] = mnew;
            u64 corrd = pack2(corr, corr);
            mul2(o2[i][0], o2[i][0], corrd);
            mul2(o2[i][1], o2[i][1], corrd);
        }

        __syncthreads();  // all Qs/Ks reads done before Ps2 overwrites them
        // Write P duplicated: Ps2[row][2j..2j+1] = (p_j, p_j)
#pragma unroll
        for (int i = 0; i < 4; i++) {
            int row = ty * 4 + i;
            ulonglong2* dst = (ulonglong2*)&Ps2[row * 128 + 8 * tx];
            dst[0] = make_ulonglong2(pack2(p[i][0], p[i][0]), pack2(p[i][1], p[i][1]));
            dst[1] = make_ulonglong2(pack2(p[i][2], p[i][2]), pack2(p[i][3], p[i][3]));
        }
        __syncthreads();

        // ---- O += P V, c-packed FFMA2 (dup P from smem, V pairs contiguous) ----
#pragma unroll 2
        for (int j4 = 0; j4 < BKT / 4; j4++) {
            ulonglong2 v0 = *(const ulonglong2*)(&Vs[(4 * j4 + 0) * HH + tx * 4]);
            ulonglong2 v1 = *(const ulonglong2*)(&Vs[(4 * j4 + 1) * HH + tx * 4]);
            ulonglong2 v2 = *(const ulonglong2*)(&Vs[(4 * j4 + 2) * HH + tx * 4]);
            ulonglong2 v3 = *(const ulonglong2*)(&Vs[(4 * j4 + 3) * HH + tx * 4]);
#pragma unroll
            for (int i = 0; i < 4; i++) {
                const float* pr = &Ps2[(ty * 4 + i) * 128 + 8 * j4];
                ulonglong2 pa = *(const ulonglong2*)(pr);
                ulonglong2 pb = *(const ulonglong2*)(pr + 4);
                fma2(o2[i][0], pa.x, v0.x);
                fma2(o2[i][1], pa.x, v0.y);
                fma2(o2[i][0], pa.y, v1.x);
                fma2(o2[i][1], pa.y, v1.y);
                fma2(o2[i][0], pb.x, v2.x);
                fma2(o2[i][1], pb.x, v2.y);
                fma2(o2[i][0], pb.y, v3.x);
                fma2(o2[i][1], pb.y, v3.y);
            }
        }
    }

    // Epilogue: write unnormalized partial + row stats
    const size_t pidx = (size_t)((b * NT + qt) * MAXSPL + split);
    float* op = g_opart + pidx * (BQ * HH);
#pragma unroll
    for (int i = 0; i < 4; i++) {
        float2 c01 = unpack2(o2[i][0]);
        float2 c23 = unpack2(o2[i][1]);
        *(float4*)(op + (ty * 4 + i) * HH + tx * 4) =
            make_float4(c01.x, c01.y, c23.x, c23.y);
        if (tx == 0) {
            g_mpart[pidx * BQ + ty * 4 + i] = m_i[i];
            g_lpart[pidx * BQ + ty * 4 + i] = l_i[i];
        }
    }
}

// ---------------------------------------------------------------------------
// Merge: combine <= MAXSPL partials per row.
// ---------------------------------------------------------------------------
__global__ __launch_bounds__(256) void merge_kernel(float* __restrict__ out)
{
    const int gid = blockIdx.x * 256 + threadIdx.x;
    const int row = gid >> 4;
    const int cx  = (gid & 15) * 4;
    const int b  = row >> 12;
    const int t  = row & (TT - 1);
    const int qt = t >> 6;
    const int r  = t & (BQ - 1);
    const int ns = (qt + CHUNK) / CHUNK;

    const size_t mlBase = (size_t)(b * NT + qt) * MAXSPL * BQ + r;

    float M = -3.0e38f;
    for (int s = 0; s < ns; s++)
        M = fmaxf(M, g_mpart[mlBase + (size_t)s * BQ]);

    float L = 0.0f;
    float a0 = 0.0f, a1 = 0.0f, a2 = 0.0f, a3 = 0.0f;
    for (int s = 0; s < ns; s++) {
        const float w = __expf(g_mpart[mlBase + (size_t)s * BQ] - M);
        L += w * g_lpart[mlBase + (size_t)s * BQ];
        const float* op = g_opart
            + (size_t)((b * NT + qt) * MAXSPL + s) * (BQ * HH) + r * HH + cx;
        float4 v = *(const float4*)op;
        a0 = fmaf(w, v.x, a0);
        a1 = fmaf(w, v.y, a1);
        a2 = fmaf(w, v.z, a2);
        a3 = fmaf(w, v.w, a3);
    }
    const float inv = 1.0f / L;
    *(float4*)(out + (size_t)row * HH + cx) =
        make_float4(a0 * inv, a1 * inv, a2 * inv, a3 * inv);
}

// ---------------------------------------------------------------------------
extern "C" void kernel_launch(void* const* d_in, const int* in_sizes, int n_in,
                              void* d_out, int out_size)
{
    const float* x  = (const float*)d_in[0];
    const float* Wk = (const float*)d_in[1];
    const float* Wq = (const float*)d_in[2];
    const float* Wv = (const float*)d_in[3];
    float* out = (float*)d_out;

    dim3 gProj((BB * TT) / 128, 3);
    proj_kernel<<<gProj, 256>>>(x, Wk, Wq, Wv);

    dim3 gAttn(NT, MAXSPL, BB);
    attn_kernel<<<gAttn, 256>>>();

    merge_kernel<<<(BB * TT * 16) / 256, 256>>>(out);
}